// round 9
// baseline (speedup 1.0000x reference)
#include <cuda_runtime.h>
#include <cuda_bf16.h>

typedef unsigned long long u64;

#define MAXN 50000
#define MAXE 800000
#define F 128

// Scratch (static device globals -- no allocation)
__device__ int   g_deg[MAXN];
__device__ int   g_off[MAXN + 1];
__device__ int   g_cur[MAXN];
__device__ int   g_adj[MAXE];
__device__ float g_hn[(size_t)MAXN * F];   // mean-aggregated neighbor features
__device__ float g_h1[(size_t)MAXN * F];   // layer-1 output
__device__ float g_h2[(size_t)MAXN * F];   // layer-2 output

// ---------------------------------------------------------------------------
// CSR build
// ---------------------------------------------------------------------------
__global__ void k_zero_deg(int n) {
    int i = blockIdx.x * blockDim.x + threadIdx.x;
    if (i < n) g_deg[i] = 0;
}

__global__ void k_count_deg(const int* __restrict__ dst, int E) {
    int i = blockIdx.x * blockDim.x + threadIdx.x;
    if (i < E) atomicAdd(&g_deg[dst[i]], 1);
}

// Single-block exclusive scan over g_deg -> g_off / g_cur. n <= 50176.
__global__ void k_scan(int n, int E) {
    __shared__ int sums[1024];
    int tid = threadIdx.x;
    int chunk = (n + 1023) >> 10;
    int b = tid * chunk;
    int e = min(b + chunk, n);
    int s = 0;
    for (int i = b; i < e; ++i) s += g_deg[i];
    sums[tid] = s;
    __syncthreads();
    for (int o = 1; o < 1024; o <<= 1) {
        int v = (tid >= o) ? sums[tid - o] : 0;
        __syncthreads();
        sums[tid] += v;
        __syncthreads();
    }
    int run = sums[tid] - s;   // exclusive prefix
    for (int i = b; i < e; ++i) {
        g_off[i] = run;
        g_cur[i] = run;
        run += g_deg[i];
    }
    if (tid == 1023) g_off[n] = E;
}

__global__ void k_fill_adj(const int* __restrict__ src, const int* __restrict__ dst, int E) {
    int i = blockIdx.x * blockDim.x + threadIdx.x;
    if (i < E) {
        int p = atomicAdd(&g_cur[dst[i]], 1);
        g_adj[p] = src[i];
    }
}

// ---------------------------------------------------------------------------
// Mean aggregation (pull via CSR): one WARP per node, lane = 4-col float4 slice.
// ---------------------------------------------------------------------------
__global__ __launch_bounds__(128) void k_agg_mean(const float* __restrict__ xext,
                                                  int layer, int N) {
    const float* __restrict__ feat = layer ? g_h1 : xext;
    int node = blockIdx.x * 4 + (threadIdx.x >> 5);
    if (node >= N) return;
    int c = (threadIdx.x & 31) * 4;

    int s = g_off[node];
    int e = g_off[node + 1];
    float4 acc = make_float4(0.f, 0.f, 0.f, 0.f);

    int j = s;
    for (; j + 2 <= e; j += 2) {
        int s0 = g_adj[j], s1 = g_adj[j + 1];
        float4 v0 = *(const float4*)&feat[(size_t)s0 * F + c];
        float4 v1 = *(const float4*)&feat[(size_t)s1 * F + c];
        acc.x += v0.x + v1.x;
        acc.y += v0.y + v1.y;
        acc.z += v0.z + v1.z;
        acc.w += v0.w + v1.w;
    }
    if (j < e) {
        float4 v = *(const float4*)&feat[(size_t)g_adj[j] * F + c];
        acc.x += v.x; acc.y += v.y; acc.z += v.z; acc.w += v.w;
    }

    int d = e - s;
    float inv = d ? 1.f / (float)d : 0.f;
    acc.x *= inv; acc.y *= inv; acc.z *= inv; acc.w *= inv;
    *(float4*)&g_hn[(size_t)node * F + c] = acc;
}

// ---------------------------------------------------------------------------
// Fused dual-GEMM + bias + ReLU, fma.rn.f32x2 inner loop, DOUBLE-BUFFERED.
//   C[m][n] = relu( sum_k A1[m][k]*W1[n][k] + sum_k A2[m][k]*W2[n][k] + bias[n] )
// Tile: 128(M) x 128(N), KB=16 per stage, 16 stages (2 srcs x 8 k-blocks).
// 256 threads, 8(M)x8(N) register tile, N packed in f32x2 pairs.
// ---------------------------------------------------------------------------
#define KB 16
#define PAD 132   // 128 + 4 floats pad: keeps 16B alignment, breaks conflicts

__device__ __forceinline__ void ffma2(u64& d, u64 a, u64 b) {
    asm("fma.rn.f32x2 %0, %1, %2, %0;" : "+l"(d) : "l"(a), "l"(b));
}
__device__ __forceinline__ u64 bcast2(float a) {
    u64 d;
    unsigned r = __float_as_uint(a);
    asm("mov.b64 %0, {%1, %1};" : "=l"(d) : "r"(r));
    return d;
}

__global__ __launch_bounds__(256) void k_gemm2(
    const float* __restrict__ xext,
    const float* __restrict__ W1, const float* __restrict__ W2,
    const float* __restrict__ bias, int M, int layer)
{
    __shared__ float At[2][KB][PAD];
    __shared__ float Wt[2][KB][PAD];

    const float* __restrict__ A1 = layer ? g_h1 : xext;
    const float* __restrict__ A2 = g_hn;
    float* __restrict__ C = layer ? g_h2 : g_h1;

    int m0 = blockIdx.x * 128;
    int tid = threadIdx.x;
    int tn = tid & 15;        // 0..15 column group (fast-varying -> coalesced C)
    int tm = tid >> 4;        // 0..15 row group

    int lr = tid >> 2;        // 0..63 : row within load slab (rows lr, lr+64)
    int lk = (tid & 3) * 4;   // 0,4,8,12 : k offset (float4)

    u64 acc2[8][4];           // [m-row][n-pair], low lane = even col
#pragma unroll
    for (int i = 0; i < 8; ++i)
#pragma unroll
        for (int j = 0; j < 4; ++j) acc2[i][j] = 0ull;

    // ---- stage s in [0,16): src = s>>3, kb = (s&7)*KB ----
    float4 ra0, ra1, rw0, rw1;

    // prologue: load stage 0 into regs, store to buffer 0
    {
        const float* A = A1;
        const float* W = W1;
        int kb = 0;
        int ma = m0 + lr, mb = m0 + lr + 64;
        ra0 = (ma < M) ? *(const float4*)&A[(size_t)ma * F + kb + lk]
                       : make_float4(0.f, 0.f, 0.f, 0.f);
        ra1 = (mb < M) ? *(const float4*)&A[(size_t)mb * F + kb + lk]
                       : make_float4(0.f, 0.f, 0.f, 0.f);
        rw0 = *(const float4*)&W[lr * F + kb + lk];
        rw1 = *(const float4*)&W[(lr + 64) * F + kb + lk];
        At[0][lk + 0][lr] = ra0.x; At[0][lk + 1][lr] = ra0.y;
        At[0][lk + 2][lr] = ra0.z; At[0][lk + 3][lr] = ra0.w;
        At[0][lk + 0][lr + 64] = ra1.x; At[0][lk + 1][lr + 64] = ra1.y;
        At[0][lk + 2][lr + 64] = ra1.z; At[0][lk + 3][lr + 64] = ra1.w;
        Wt[0][lk + 0][lr] = rw0.x; Wt[0][lk + 1][lr] = rw0.y;
        Wt[0][lk + 2][lr] = rw0.z; Wt[0][lk + 3][lr] = rw0.w;
        Wt[0][lk + 0][lr + 64] = rw1.x; Wt[0][lk + 1][lr + 64] = rw1.y;
        Wt[0][lk + 2][lr + 64] = rw1.z; Wt[0][lk + 3][lr + 64] = rw1.w;
    }
    __syncthreads();

#pragma unroll 1
    for (int s = 0; s < 16; ++s) {
        int buf = s & 1;
        bool more = (s < 15);

        // prefetch stage s+1 to registers (hidden under math below)
        if (more) {
            int sn = s + 1;
            const float* A = (sn & 8) ? A2 : A1;
            const float* W = (sn & 8) ? W2 : W1;
            int kb = (sn & 7) * KB;
            int ma = m0 + lr, mb = m0 + lr + 64;
            ra0 = (ma < M) ? *(const float4*)&A[(size_t)ma * F + kb + lk]
                           : make_float4(0.f, 0.f, 0.f, 0.f);
            ra1 = (mb < M) ? *(const float4*)&A[(size_t)mb * F + kb + lk]
                           : make_float4(0.f, 0.f, 0.f, 0.f);
            rw0 = *(const float4*)&W[lr * F + kb + lk];
            rw1 = *(const float4*)&W[(lr + 64) * F + kb + lk];
        }

        // math on current buffer
#pragma unroll
        for (int kk = 0; kk < KB; ++kk) {
            float4 a0 = *(const float4*)&At[buf][kk][tm * 8];
            float4 a1 = *(const float4*)&At[buf][kk][tm * 8 + 4];
            ulonglong2 wq0 = *(const ulonglong2*)&Wt[buf][kk][tn * 8];
            ulonglong2 wq1 = *(const ulonglong2*)&Wt[buf][kk][tn * 8 + 4];
            u64 w2[4] = {wq0.x, wq0.y, wq1.x, wq1.y};

            u64 ap[8];
            ap[0] = bcast2(a0.x); ap[1] = bcast2(a0.y);
            ap[2] = bcast2(a0.z); ap[3] = bcast2(a0.w);
            ap[4] = bcast2(a1.x); ap[5] = bcast2(a1.y);
            ap[6] = bcast2(a1.z); ap[7] = bcast2(a1.w);
#pragma unroll
            for (int i = 0; i < 8; ++i)
#pragma unroll
                for (int j = 0; j < 4; ++j)
                    ffma2(acc2[i][j], ap[i], w2[j]);
        }

        // commit prefetched stage to the other buffer
        if (more) {
            int nb = buf ^ 1;
            At[nb][lk + 0][lr] = ra0.x; At[nb][lk + 1][lr] = ra0.y;
            At[nb][lk + 2][lr] = ra0.z; At[nb][lk + 3][lr] = ra0.w;
            At[nb][lk + 0][lr + 64] = ra1.x; At[nb][lk + 1][lr + 64] = ra1.y;
            At[nb][lk + 2][lr + 64] = ra1.z; At[nb][lk + 3][lr + 64] = ra1.w;
            Wt[nb][lk + 0][lr] = rw0.x; Wt[nb][lk + 1][lr] = rw0.y;
            Wt[nb][lk + 2][lr] = rw0.z; Wt[nb][lk + 3][lr] = rw0.w;
            Wt[nb][lk + 0][lr + 64] = rw1.x; Wt[nb][lk + 1][lr + 64] = rw1.y;
            Wt[nb][lk + 2][lr + 64] = rw1.z; Wt[nb][lk + 3][lr + 64] = rw1.w;
            __syncthreads();
        }
    }

    // Epilogue: unpack, bias + relu, float4 stores
    float bv[8];
#pragma unroll
    for (int j = 0; j < 8; ++j) bv[j] = bias[tn * 8 + j];

#pragma unroll
    for (int i = 0; i < 8; ++i) {
        int m = m0 + tm * 8 + i;
        if (m < M) {
            float c8[8];
#pragma unroll
            for (int j = 0; j < 4; ++j) {
                u64 v = acc2[i][j];
                c8[2 * j + 0] = __uint_as_float((unsigned)v);
                c8[2 * j + 1] = __uint_as_float((unsigned)(v >> 32));
            }
            float4 o0, o1;
            o0.x = fmaxf(c8[0] + bv[0], 0.f);
            o0.y = fmaxf(c8[1] + bv[1], 0.f);
            o0.z = fmaxf(c8[2] + bv[2], 0.f);
            o0.w = fmaxf(c8[3] + bv[3], 0.f);
            o1.x = fmaxf(c8[4] + bv[4], 0.f);
            o1.y = fmaxf(c8[5] + bv[5], 0.f);
            o1.z = fmaxf(c8[6] + bv[6], 0.f);
            o1.w = fmaxf(c8[7] + bv[7], 0.f);
            *(float4*)&C[(size_t)m * F + tn * 8] = o0;
            *(float4*)&C[(size_t)m * F + tn * 8 + 4] = o1;
        }
    }
}

// ---------------------------------------------------------------------------
// Readout: states max-pool + action row, dot with Wfc, +bfc -> scalar
// ---------------------------------------------------------------------------
__global__ void k_readout(const int* __restrict__ states, int S,
                          const int* __restrict__ actions,
                          const float* __restrict__ Wfc,
                          const float* __restrict__ bfc,
                          float* __restrict__ out)
{
    __shared__ int   snode[512];
    __shared__ float red[128];
    int c = threadIdx.x;   // 128 threads
    for (int i = c; i < S; i += 128) snode[i] = states[i];
    __syncthreads();

    float m = -3.4e38f;
    int s2 = 0;
    for (; s2 + 4 <= S; s2 += 4) {
        float v0 = g_h2[(size_t)snode[s2 + 0] * F + c];
        float v1 = g_h2[(size_t)snode[s2 + 1] * F + c];
        float v2 = g_h2[(size_t)snode[s2 + 2] * F + c];
        float v3 = g_h2[(size_t)snode[s2 + 3] * F + c];
        m = fmaxf(m, fmaxf(fmaxf(v0, v1), fmaxf(v2, v3)));
    }
    for (; s2 < S; ++s2) m = fmaxf(m, g_h2[(size_t)snode[s2] * F + c]);

    float a = g_h2[(size_t)actions[0] * F + c];
    float p = m * Wfc[c] + a * Wfc[F + c];
    red[c] = p;
    __syncthreads();
    for (int o = 64; o > 0; o >>= 1) {
        if (c < o) red[c] += red[c + o];
        __syncthreads();
    }
    if (c == 0) out[0] = red[0] + bfc[0];
}

// ---------------------------------------------------------------------------
extern "C" void kernel_launch(void* const* d_in, const int* in_sizes, int n_in,
                              void* d_out, int out_size)
{
    const float* x       = (const float*)d_in[0];
    const int*   esrc    = (const int*)d_in[1];
    const int*   edst    = (const int*)d_in[2];
    const int*   states  = (const int*)d_in[3];
    const int*   actions = (const int*)d_in[4];
    const float* W1s     = (const float*)d_in[5];
    const float* W1n     = (const float*)d_in[6];
    const float* b1      = (const float*)d_in[7];
    const float* W2s     = (const float*)d_in[8];
    const float* W2n     = (const float*)d_in[9];
    const float* b2      = (const float*)d_in[10];
    const float* Wfc     = (const float*)d_in[11];
    const float* bfc     = (const float*)d_in[12];
    float* out = (float*)d_out;

    int N = in_sizes[0] / F;
    int E = in_sizes[1];
    int S = in_sizes[3];

    // CSR build (per launch; identical work every call)
    k_zero_deg<<<(N + 255) / 256, 256>>>(N);
    k_count_deg<<<(E + 255) / 256, 256>>>(edst, E);
    k_scan<<<1, 1024>>>(N, E);
    k_fill_adj<<<(E + 255) / 256, 256>>>(esrc, edst, E);

    int gemm_blocks = (N + 127) / 128;
    int agg_blocks = (N + 3) / 4;

    // Layer 1
    k_agg_mean<<<agg_blocks, 128>>>(x, 0, N);
    k_gemm2<<<gemm_blocks, 256>>>(x, W1s, W1n, b1, N, 0);

    // Layer 2
    k_agg_mean<<<agg_blocks, 128>>>(x, 1, N);
    k_gemm2<<<gemm_blocks, 256>>>(x, W2s, W2n, b2, N, 1);

    // Readout
    k_readout<<<1, 128>>>(states, S, actions, Wfc, bfc, out);
}